// round 1
// baseline (speedup 1.0000x reference)
#include <cuda_runtime.h>

// Problem constants (fixed by the dataset)
#define L_SEQ 8192
#define H 128
#define TT 4095          // (8192-3)/2 + 1
#define NC 128           // scan chunks
#define LC 32            // chunk length (last chunk = 31)
#define NELEM (H * H)    // 16384 state elements

// Scratch (allocation-free rule: __device__ globals)
static __device__ float g_Y[TT * 3 * H];            // Y[t][w][d] = (w_q @ X_t)[w,d]   ~6.3 MB
static __device__ float g_S[NC * NELEM];            // chunk-local end states          8 MB
static __device__ float g_cin[NC * NELEM];          // carry-in per chunk              8 MB
static __device__ float g_zs[(size_t)TT * NELEM];   // materialized scan states        268 MB

// ---------------------------------------------------------------------------
// Kernel 1: precompute Y[t][w][:] = sum_v wq[w][v] * input[2t+v][:]
//           and os[t][:] = sum_w D[w] * input[2t+w][:]
// ---------------------------------------------------------------------------
__global__ void prep_kernel(const float* __restrict__ in,
                            const float* __restrict__ wq,
                            const float* __restrict__ Dv,
                            float* __restrict__ os_out) {
    int t = blockIdx.x;
    int d = threadIdx.x;
    float x0 = in[(2 * t + 0) * H + d];
    float x1 = in[(2 * t + 1) * H + d];
    float x2 = in[(2 * t + 2) * H + d];
    g_Y[(t * 3 + 0) * H + d] = wq[0] * x0 + wq[1] * x1 + wq[2] * x2;
    g_Y[(t * 3 + 1) * H + d] = wq[3] * x0 + wq[4] * x1 + wq[5] * x2;
    g_Y[(t * 3 + 2) * H + d] = wq[6] * x0 + wq[7] * x1 + wq[8] * x2;
    os_out[t * H + d] = Dv[0] * x0 + Dv[1] * x1 + Dv[2] * x2;
}

// ---------------------------------------------------------------------------
// Kernels 2 & 4: chunked scan over t.
// PASS 0: start from 0, emit chunk end-state into g_S.
// PASS 1: start from carry-in (g_cin), emit every z_t into g_zs.
// Grid: (8 a-tiles of 16, NC chunks). Block: 256 threads.
// Thread owns 8 (a,d) elements: d = tid&127, a = a0 + (tid>>7)*8 + k.
// ---------------------------------------------------------------------------
template <int PASS>
__global__ __launch_bounds__(256) void scan_pass_kernel(const float* __restrict__ in,
                                                        const float* __restrict__ Lam) {
    __shared__ float Xs[3 * 16];    // X[w][a_local]
    __shared__ float Ys[3 * H];     // Y[w][d]

    int c   = blockIdx.y;
    int a0  = blockIdx.x * 16;
    int tid = threadIdx.x;
    int d   = tid & 127;
    int ah  = (tid >> 7) * 8;       // 0 or 8

    float z[8], lam[8];
#pragma unroll
    for (int k = 0; k < 8; k++) {
        int a = a0 + ah + k;
        lam[k] = Lam[a * H + d];
        if (PASS == 0)
            z[k] = 0.0f;
        else
            z[k] = g_cin[c * NELEM + a * H + d];
    }

    int t0 = c * LC;
    int t1 = t0 + LC;
    if (t1 > TT) t1 = TT;

    for (int t = t0; t < t1; t++) {
        // stage Y[t] and the 3x16 X slice for this a-tile
        for (int i = tid; i < 3 * H; i += 256) Ys[i] = g_Y[t * (3 * H) + i];
        if (tid < 48) {
            int w = tid / 16, al = tid % 16;
            Xs[tid] = in[(2 * t + w) * H + a0 + al];
        }
        __syncthreads();

        float y0 = Ys[0 * H + d];
        float y1 = Ys[1 * H + d];
        float y2 = Ys[2 * H + d];
#pragma unroll
        for (int k = 0; k < 8; k++) {
            int al = ah + k;
            float u = Xs[al] * y0 + Xs[16 + al] * y1 + Xs[32 + al] * y2;
            z[k] = fmaf(lam[k], z[k], u);
        }
        if (PASS == 1) {
            size_t base = (size_t)t * NELEM + (size_t)(a0 + ah) * H + d;
#pragma unroll
            for (int k = 0; k < 8; k++) g_zs[base + (size_t)k * H] = z[k];
        }
        __syncthreads();
    }

    if (PASS == 0) {
#pragma unroll
        for (int k = 0; k < 8; k++) g_S[c * NELEM + (a0 + ah + k) * H + d] = z[k];
    }
}

// ---------------------------------------------------------------------------
// Kernel 3: sequential carry combine across chunks (depth NC, trivially parallel
// over the 16384 state elements). carry_in[c] = lam^LC * carry_in[c-1] + S[c-1].
// ---------------------------------------------------------------------------
__global__ void combine_kernel(const float* __restrict__ Lam) {
    int e = blockIdx.x * 256 + threadIdx.x;   // 0..16383 : e = a*H + d
    float lam = Lam[e];
    float p = lam;                            // lam^32 via 5 squarings
    p = p * p; p = p * p; p = p * p; p = p * p; p = p * p;
    float cin = 0.0f;
    for (int c = 0; c < NC; c++) {
        g_cin[c * NELEM + e] = cin;
        cin = fmaf(p, cin, g_S[c * NELEM + e]);
    }
}

// ---------------------------------------------------------------------------
// Kernel 5: batched GEMM  out[t][h][a] = sum_d C[h][d] * zs[t][a][d]
// One CTA per t, 256 threads, 8x8 register tile per thread,
// k staged through SMEM in chunks of 32 (dd-major, padded stride 132).
// ---------------------------------------------------------------------------
__global__ __launch_bounds__(256) void gemm_kernel(const float* __restrict__ Cm,
                                                   float* __restrict__ out) {
    __shared__ float Cs[32][132];   // Cs[dd][h]
    __shared__ float Zs[32][132];   // Zs[dd][a]

    int t   = blockIdx.x;
    int tid = threadIdx.x;
    int tx  = tid & 15;     // a-group
    int ty  = tid >> 4;     // h-group

    float acc[8][8];
#pragma unroll
    for (int i = 0; i < 8; i++)
#pragma unroll
        for (int j = 0; j < 8; j++) acc[i][j] = 0.0f;

    const float* zt = g_zs + (size_t)t * NELEM;

    for (int d0 = 0; d0 < H; d0 += 32) {
        for (int i = tid; i < 128 * 32; i += 256) {
            int r  = i >> 5;    // h or a row, global loads coalesced over dd
            int dd = i & 31;
            Cs[dd][r] = Cm[r * H + d0 + dd];
            Zs[dd][r] = zt[r * H + d0 + dd];
        }
        __syncthreads();

#pragma unroll
        for (int dd = 0; dd < 32; dd++) {
            float4 c0 = *(const float4*)&Cs[dd][ty * 8];
            float4 c1 = *(const float4*)&Cs[dd][ty * 8 + 4];
            float4 z0 = *(const float4*)&Zs[dd][tx * 8];
            float4 z1 = *(const float4*)&Zs[dd][tx * 8 + 4];
            float ch[8] = {c0.x, c0.y, c0.z, c0.w, c1.x, c1.y, c1.z, c1.w};
            float za[8] = {z0.x, z0.y, z0.z, z0.w, z1.x, z1.y, z1.z, z1.w};
#pragma unroll
            for (int i = 0; i < 8; i++)
#pragma unroll
                for (int j = 0; j < 8; j++)
                    acc[i][j] = fmaf(ch[i], za[j], acc[i][j]);
        }
        __syncthreads();
    }

    float* ot = out + (size_t)t * NELEM;
#pragma unroll
    for (int i = 0; i < 8; i++) {
        int h = ty * 8 + i;
        float4 v0 = make_float4(acc[i][0], acc[i][1], acc[i][2], acc[i][3]);
        float4 v1 = make_float4(acc[i][4], acc[i][5], acc[i][6], acc[i][7]);
        *(float4*)&ot[h * H + tx * 8]     = v0;
        *(float4*)&ot[h * H + tx * 8 + 4] = v1;
    }
}

// ---------------------------------------------------------------------------
// Launch: prep -> chunk scan (pass 0) -> combine -> seeded scan (pass 1) -> GEMM
// Output layout: zs_out (T*H*H floats) followed by os (T*H floats).
// ---------------------------------------------------------------------------
extern "C" void kernel_launch(void* const* d_in, const int* in_sizes, int n_in,
                              void* d_out, int out_size) {
    const float* in  = (const float*)d_in[0];   // input_sequence (8192,128)
    const float* lam = (const float*)d_in[1];   // Lambda_bar (128,128)
    const float* Cm  = (const float*)d_in[2];   // C_tilde (128,128)
    const float* wq  = (const float*)d_in[3];   // w_q (3,3)
    const float* Dv  = (const float*)d_in[4];   // D (3,)
    (void)in_sizes; (void)n_in; (void)out_size;

    float* out    = (float*)d_out;
    float* os_out = out + (size_t)TT * NELEM;

    prep_kernel<<<TT, H>>>(in, wq, Dv, os_out);
    scan_pass_kernel<0><<<dim3(8, NC), 256>>>(in, lam);
    combine_kernel<<<NELEM / 256, 256>>>(lam);
    scan_pass_kernel<1><<<dim3(8, NC), 256>>>(in, lam);
    gemm_kernel<<<TT, 256>>>(Cm, out);
}

// round 2
// speedup vs baseline: 2.9328x; 2.9328x over previous
#include <cuda_runtime.h>
#include <cstdint>

// Problem constants (fixed by the dataset)
#define H 128
#define TT 4095          // (8192-3)/2 + 1
#define NC 128           // scan chunks
#define LC 32            // chunk length (last chunk = 31)
#define NELEM (H * H)    // 16384 state elements
#define ZS_STRIDE 132    // padded ta-major Z row stride (conflict-free B loads)

// Scratch (allocation-free rule: __device__ globals)
static __device__ float g_Y[TT * 3 * H];   // Y[t][w][d] = (w_q @ X_t)[w,d]
static __device__ float g_S[NC * NELEM];   // chunk-local end states
static __device__ float g_cin[NC * NELEM]; // carry-in per chunk

static __device__ __forceinline__ uint32_t f2tf32(float v) {
    uint32_t r;
    asm("cvt.rna.tf32.f32 %0, %1;" : "=r"(r) : "f"(v));
    return r;
}

// ---------------------------------------------------------------------------
// Kernel 1: Y[t][w][:] = sum_v wq[w][v] * x[2t+v][:],  os[t][:] = sum_w D[w]*x[2t+w][:]
// ---------------------------------------------------------------------------
__global__ void prep_kernel(const float* __restrict__ in,
                            const float* __restrict__ wq,
                            const float* __restrict__ Dv,
                            float* __restrict__ os_out) {
    int t = blockIdx.x;
    int d = threadIdx.x;
    float x0 = in[(2 * t + 0) * H + d];
    float x1 = in[(2 * t + 1) * H + d];
    float x2 = in[(2 * t + 2) * H + d];
    g_Y[(t * 3 + 0) * H + d] = wq[0] * x0 + wq[1] * x1 + wq[2] * x2;
    g_Y[(t * 3 + 1) * H + d] = wq[3] * x0 + wq[4] * x1 + wq[5] * x2;
    g_Y[(t * 3 + 2) * H + d] = wq[6] * x0 + wq[7] * x1 + wq[8] * x2;
    os_out[t * H + d] = Dv[0] * x0 + Dv[1] * x1 + Dv[2] * x2;
}

// ---------------------------------------------------------------------------
// Kernel 2: chunk-local scan (zero init), batch-staged (8 t per barrier pair).
// Grid (8 a-tiles, NC chunks), 256 threads. Thread: d = tid&127, 8 a's.
// ---------------------------------------------------------------------------
__global__ __launch_bounds__(256) void scan0_kernel(const float* __restrict__ in,
                                                    const float* __restrict__ Lam) {
    __shared__ float Ys[8 * 384];
    __shared__ float Xs[8 * 48];

    int c   = blockIdx.y;
    int a0  = blockIdx.x * 16;
    int tid = threadIdx.x;
    int d   = tid & 127;
    int ah  = (tid >> 7) * 8;

    float z[8], lam[8];
#pragma unroll
    for (int k = 0; k < 8; k++) {
        lam[k] = Lam[(a0 + ah + k) * H + d];
        z[k]   = 0.0f;
    }

    int t0c = c * LC;
    int t1c = t0c + LC; if (t1c > TT) t1c = TT;

    for (int tb = t0c; tb < t1c; tb += 8) {
        int nvt = t1c - tb; if (nvt > 8) nvt = 8;
        for (int i = tid; i < nvt * 384; i += 256) Ys[i] = g_Y[tb * 384 + i];
        for (int i = tid; i < nvt * 48; i += 256) {
            int tl = i / 48, r = i % 48, w = r / 16, al = r % 16;
            Xs[i] = in[(2 * (tb + tl) + w) * H + a0 + al];
        }
        __syncthreads();
        for (int tl = 0; tl < nvt; tl++) {
            float y0 = Ys[tl * 384 + d];
            float y1 = Ys[tl * 384 + 128 + d];
            float y2 = Ys[tl * 384 + 256 + d];
            const float* xs = &Xs[tl * 48 + ah];
#pragma unroll
            for (int k = 0; k < 8; k++) {
                float u = xs[k] * y0 + xs[16 + k] * y1 + xs[32 + k] * y2;
                z[k] = fmaf(lam[k], z[k], u);
            }
        }
        __syncthreads();
    }

#pragma unroll
    for (int k = 0; k < 8; k++) g_S[c * NELEM + (a0 + ah + k) * H + d] = z[k];
}

// ---------------------------------------------------------------------------
// Kernel 3: sequential carry combine across chunks.
// ---------------------------------------------------------------------------
__global__ void combine_kernel(const float* __restrict__ Lam) {
    int e = blockIdx.x * 256 + threadIdx.x;
    float lam = Lam[e];
    float p = lam;  // lam^32 via 5 squarings
    p = p * p; p = p * p; p = p * p; p = p * p; p = p * p;
    float cin = 0.0f;
    for (int c = 0; c < NC; c++) {
        g_cin[c * NELEM + e] = cin;
        cin = fmaf(p, cin, g_S[c * NELEM + e]);
    }
}

// ---------------------------------------------------------------------------
// Kernel 4: FUSED seeded scan + TF32 tensor-core GEMM.
// Per CTA (a-tile of 16, chunk of 32 t): batches of 8 t.
//   scan  -> Zs[ta][d] (ta = tl*16 + a_local), tf32-rounded
//   GEMM  -> out[t][h][a0+a] = sum_d C[h][d] * z[t][a][d]
//            8 warps; warp w owns 16 h-rows; A frags (C) held in registers.
// ---------------------------------------------------------------------------
__global__ __launch_bounds__(256, 2) void fused_kernel(const float* __restrict__ in,
                                                       const float* __restrict__ Lam,
                                                       const float* __restrict__ Cm,
                                                       float* __restrict__ out) {
    extern __shared__ float smem[];
    float* Zs = smem;                      // 128 * 132
    float* Ys = Zs + 128 * ZS_STRIDE;      // 8 * 384
    float* Xs = Ys + 8 * 384;              // 8 * 48

    int c   = blockIdx.y;
    int a0  = blockIdx.x * 16;
    int tid = threadIdx.x;
    int d   = tid & 127;
    int ah  = (tid >> 7) * 8;

    int wrp = tid >> 5;          // 0..7
    int l   = tid & 31;
    int grp = l >> 2;            // l/4
    int thr = l & 3;             // l%4
    int h0  = wrp * 16;

    // A fragments: C rows [h0, h0+16), all 128 d, tf32. 16 k-tiles x 4 regs.
    uint32_t afr[16][4];
#pragma unroll
    for (int kt = 0; kt < 16; kt++) {
        int col = kt * 8 + thr;
        afr[kt][0] = f2tf32(Cm[(h0 + grp) * H + col]);
        afr[kt][1] = f2tf32(Cm[(h0 + grp + 8) * H + col]);
        afr[kt][2] = f2tf32(Cm[(h0 + grp) * H + col + 4]);
        afr[kt][3] = f2tf32(Cm[(h0 + grp + 8) * H + col + 4]);
    }

    float z[8], lam[8];
#pragma unroll
    for (int k = 0; k < 8; k++) {
        int a = a0 + ah + k;
        lam[k] = Lam[a * H + d];
        z[k]   = g_cin[c * NELEM + a * H + d];
    }

    int t0c = c * LC;
    int t1c = t0c + LC; if (t1c > TT) t1c = TT;

    for (int tb = t0c; tb < t1c; tb += 8) {
        int nvt = t1c - tb; if (nvt > 8) nvt = 8;

        // stage Y and X for this batch (does not touch Zs)
        for (int i = tid; i < nvt * 384; i += 256) Ys[i] = g_Y[tb * 384 + i];
        for (int i = tid; i < nvt * 48; i += 256) {
            int tl = i / 48, r = i % 48, w = r / 16, al = r % 16;
            Xs[i] = in[(2 * (tb + tl) + w) * H + a0 + al];
        }
        __syncthreads();   // Ys/Xs ready AND previous batch's GEMM done with Zs

        // scan 8 timesteps, write tf32-rounded states into Zs[ta][d]
        for (int tl = 0; tl < nvt; tl++) {
            float y0 = Ys[tl * 384 + d];
            float y1 = Ys[tl * 384 + 128 + d];
            float y2 = Ys[tl * 384 + 256 + d];
            const float* xs = &Xs[tl * 48 + ah];
#pragma unroll
            for (int k = 0; k < 8; k++) {
                float u = xs[k] * y0 + xs[16 + k] * y1 + xs[32 + k] * y2;
                z[k] = fmaf(lam[k], z[k], u);
                Zs[(tl * 16 + ah + k) * ZS_STRIDE + d] = __uint_as_float(f2tf32(z[k]));
            }
        }
        __syncthreads();   // Zs ready

        // GEMM: out tile 128h x (nvt*16)ta, m16n8k8 tf32
        for (int nt = 0; nt < 16; nt++) {
            int tl = nt >> 1;
            int t  = tb + tl;
            if (t >= TT) break;
            float d0 = 0.f, d1 = 0.f, d2 = 0.f, d3 = 0.f;
            const float* zb = Zs + (nt * 8 + grp) * ZS_STRIDE + thr;
#pragma unroll
            for (int kt = 0; kt < 16; kt++) {
                uint32_t b0 = __float_as_uint(zb[kt * 8]);
                uint32_t b1 = __float_as_uint(zb[kt * 8 + 4]);
                asm volatile(
                    "mma.sync.aligned.m16n8k8.row.col.f32.tf32.tf32.f32 "
                    "{%0,%1,%2,%3}, {%4,%5,%6,%7}, {%8,%9}, {%0,%1,%2,%3};"
                    : "+f"(d0), "+f"(d1), "+f"(d2), "+f"(d3)
                    : "r"(afr[kt][0]), "r"(afr[kt][1]), "r"(afr[kt][2]), "r"(afr[kt][3]),
                      "r"(b0), "r"(b1));
            }
            size_t ob = (size_t)t * NELEM + (size_t)(h0 + grp) * H
                      + a0 + (nt & 1) * 8 + 2 * thr;
            *(float2*)&out[ob]           = make_float2(d0, d1);
            *(float2*)&out[ob + 8 * H]   = make_float2(d2, d3);
        }
    }
}

// ---------------------------------------------------------------------------
// Launch: prep -> scan0 -> combine -> fused(scan+GEMM)
// Output layout: zs_out (T*H*H floats) followed by os (T*H floats).
// ---------------------------------------------------------------------------
extern "C" void kernel_launch(void* const* d_in, const int* in_sizes, int n_in,
                              void* d_out, int out_size) {
    const float* in  = (const float*)d_in[0];   // input_sequence (8192,128)
    const float* lam = (const float*)d_in[1];   // Lambda_bar (128,128)
    const float* Cm  = (const float*)d_in[2];   // C_tilde (128,128)
    const float* wq  = (const float*)d_in[3];   // w_q (3,3)
    const float* Dv  = (const float*)d_in[4];   // D (3,)
    (void)in_sizes; (void)n_in; (void)out_size;

    float* out    = (float*)d_out;
    float* os_out = out + (size_t)TT * NELEM;

    const int fused_smem = (128 * ZS_STRIDE + 8 * 384 + 8 * 48) * (int)sizeof(float);
    cudaFuncSetAttribute(fused_kernel, cudaFuncAttributeMaxDynamicSharedMemorySize,
                         fused_smem);

    prep_kernel<<<TT, H>>>(in, wq, Dv, os_out);
    scan0_kernel<<<dim3(8, NC), 256>>>(in, lam);
    combine_kernel<<<NELEM / 256, 256>>>(lam);
    fused_kernel<<<dim3(8, NC), 256, fused_smem>>>(in, lam, Cm, out);
}

// round 3
// speedup vs baseline: 3.4605x; 1.1799x over previous
#include <cuda_runtime.h>
#include <cuda_fp16.h>
#include <cstdint>

// Problem constants (fixed by the dataset)
#define H 128
#define TT 4095          // (8192-3)/2 + 1
#define NC 128           // scan chunks
#define LC 32            // chunk length (last chunk = 31)
#define NELEM (H * H)    // 16384 state elements
#define ZSH 136          // padded Zs row stride in halves (conflict-free)

// Scratch (allocation-free rule: __device__ globals)
static __device__ float g_Y[TT * 3 * H];   // Y[t][w][d] = (w_q @ X_t)[w,d]
static __device__ float g_S[NC * NELEM];   // chunk-local end states
static __device__ float g_cin[NC * NELEM]; // carry-in per chunk

// ---------------------------------------------------------------------------
// Kernel 1: Y[t][w][:] = sum_v wq[w][v] * x[2t+v][:],  os[t][:] = sum_w D[w]*x[2t+w][:]
// ---------------------------------------------------------------------------
__global__ void prep_kernel(const float* __restrict__ in,
                            const float* __restrict__ wq,
                            const float* __restrict__ Dv,
                            float* __restrict__ os_out) {
    int t = blockIdx.x;
    int d = threadIdx.x;
    float x0 = in[(2 * t + 0) * H + d];
    float x1 = in[(2 * t + 1) * H + d];
    float x2 = in[(2 * t + 2) * H + d];
    g_Y[(t * 3 + 0) * H + d] = wq[0] * x0 + wq[1] * x1 + wq[2] * x2;
    g_Y[(t * 3 + 1) * H + d] = wq[3] * x0 + wq[4] * x1 + wq[5] * x2;
    g_Y[(t * 3 + 2) * H + d] = wq[6] * x0 + wq[7] * x1 + wq[8] * x2;
    os_out[t * H + d] = Dv[0] * x0 + Dv[1] * x1 + Dv[2] * x2;
}

// ---------------------------------------------------------------------------
// Kernel 2: chunk-local scan (zero init), batch-staged (8 t per barrier pair).
// ---------------------------------------------------------------------------
__global__ __launch_bounds__(256) void scan0_kernel(const float* __restrict__ in,
                                                    const float* __restrict__ Lam) {
    __shared__ float Ys[8 * 384];
    __shared__ float Xs[8 * 48];

    int c   = blockIdx.y;
    int a0  = blockIdx.x * 16;
    int tid = threadIdx.x;
    int d   = tid & 127;
    int ah  = (tid >> 7) * 8;

    float z[8], lam[8];
#pragma unroll
    for (int k = 0; k < 8; k++) {
        lam[k] = Lam[(a0 + ah + k) * H + d];
        z[k]   = 0.0f;
    }

    int t0c = c * LC;
    int t1c = t0c + LC; if (t1c > TT) t1c = TT;

    for (int tb = t0c; tb < t1c; tb += 8) {
        int nvt = t1c - tb; if (nvt > 8) nvt = 8;
        for (int i = tid; i < nvt * 384; i += 256) Ys[i] = g_Y[tb * 384 + i];
        for (int i = tid; i < nvt * 48; i += 256) {
            int tl = i / 48, r = i % 48, w = r / 16, al = r % 16;
            Xs[i] = in[(2 * (tb + tl) + w) * H + a0 + al];
        }
        __syncthreads();
        for (int tl = 0; tl < nvt; tl++) {
            float y0 = Ys[tl * 384 + d];
            float y1 = Ys[tl * 384 + 128 + d];
            float y2 = Ys[tl * 384 + 256 + d];
            const float* xs = &Xs[tl * 48 + ah];
#pragma unroll
            for (int k = 0; k < 8; k++) {
                float u = xs[k] * y0 + xs[16 + k] * y1 + xs[32 + k] * y2;
                z[k] = fmaf(lam[k], z[k], u);
            }
        }
        __syncthreads();
    }

#pragma unroll
    for (int k = 0; k < 8; k++) g_S[c * NELEM + (a0 + ah + k) * H + d] = z[k];
}

// ---------------------------------------------------------------------------
// Kernel 3: sequential carry combine across chunks.
// ---------------------------------------------------------------------------
__global__ void combine_kernel(const float* __restrict__ Lam) {
    int e = blockIdx.x * 256 + threadIdx.x;
    float lam = Lam[e];
    float p = lam;  // lam^32 via 5 squarings
    p = p * p; p = p * p; p = p * p; p = p * p; p = p * p;
    float cin = 0.0f;
    for (int c = 0; c < NC; c++) {
        g_cin[c * NELEM + e] = cin;
        cin = fmaf(p, cin, g_S[c * NELEM + e]);
    }
}

// ---------------------------------------------------------------------------
// Kernel 4: FUSED seeded scan + FP16 tensor-core GEMM (m16n8k16, f32 accum).
// Per CTA (a-tile of 16, chunk of 32 t): batches of 8 t.
//   scan  -> Zs[ta][d] as fp16 (ta = tl*16 + a_local)
//   GEMM  -> out[t][h][a0+a] = sum_d C[h][d] * z[t][a][d]
//            8 warps; warp w owns 16 h-rows; A frags (C, fp16) in registers.
// ---------------------------------------------------------------------------
__global__ __launch_bounds__(256, 2) void fused_kernel(const float* __restrict__ in,
                                                       const float* __restrict__ Lam,
                                                       const float* __restrict__ Cm,
                                                       float* __restrict__ out) {
    extern __shared__ float smem[];
    __half* Zs = (__half*)smem;                       // 128 * ZSH halves
    float*  Ys = smem + (128 * ZSH + 1) / 2;          // 8 * 384
    float*  Xs = Ys + 8 * 384;                        // 8 * 48

    int c   = blockIdx.y;
    int a0  = blockIdx.x * 16;
    int tid = threadIdx.x;
    int d   = tid & 127;
    int ah  = (tid >> 7) * 8;

    int wrp = tid >> 5;          // 0..7
    int l   = tid & 31;
    int grp = l >> 2;            // l/4
    int thr = l & 3;             // l%4
    int h0  = wrp * 16;

    // A fragments: C rows [h0, h0+16), fp16. 8 k-tiles (k16 each) x 4 half2 regs.
    uint32_t afr[8][4];
#pragma unroll
    for (int kt = 0; kt < 8; kt++) {
        int cb = kt * 16 + 2 * thr;
        const float* r0 = Cm + (h0 + grp) * H;
        const float* r1 = Cm + (h0 + grp + 8) * H;
        __half2 a0h = __floats2half2_rn(r0[cb],     r0[cb + 1]);
        __half2 a1h = __floats2half2_rn(r1[cb],     r1[cb + 1]);
        __half2 a2h = __floats2half2_rn(r0[cb + 8], r0[cb + 9]);
        __half2 a3h = __floats2half2_rn(r1[cb + 8], r1[cb + 9]);
        afr[kt][0] = *(uint32_t*)&a0h;
        afr[kt][1] = *(uint32_t*)&a1h;
        afr[kt][2] = *(uint32_t*)&a2h;
        afr[kt][3] = *(uint32_t*)&a3h;
    }

    float z[8], lam[8];
#pragma unroll
    for (int k = 0; k < 8; k++) {
        int a = a0 + ah + k;
        lam[k] = Lam[a * H + d];
        z[k]   = g_cin[c * NELEM + a * H + d];
    }

    int t0c = c * LC;
    int t1c = t0c + LC; if (t1c > TT) t1c = TT;

    for (int tb = t0c; tb < t1c; tb += 8) {
        int nvt = t1c - tb; if (nvt > 8) nvt = 8;

        // stage Y and X for this batch
        for (int i = tid; i < nvt * 384; i += 256) Ys[i] = g_Y[tb * 384 + i];
        for (int i = tid; i < nvt * 48; i += 256) {
            int tl = i / 48, r = i % 48, w = r / 16, al = r % 16;
            Xs[i] = in[(2 * (tb + tl) + w) * H + a0 + al];
        }
        __syncthreads();   // Ys/Xs ready AND previous batch's GEMM done with Zs

        // scan 8 timesteps, write fp16 states into Zs[ta][d]
        for (int tl = 0; tl < nvt; tl++) {
            float y0 = Ys[tl * 384 + d];
            float y1 = Ys[tl * 384 + 128 + d];
            float y2 = Ys[tl * 384 + 256 + d];
            const float* xs = &Xs[tl * 48 + ah];
#pragma unroll
            for (int k = 0; k < 8; k++) {
                float u = xs[k] * y0 + xs[16 + k] * y1 + xs[32 + k] * y2;
                z[k] = fmaf(lam[k], z[k], u);
                Zs[(tl * 16 + ah + k) * ZSH + d] = __float2half(z[k]);
            }
        }
        __syncthreads();   // Zs ready

        // GEMM: out tile 128h x (nvt*16)ta, m16n8k16 fp16->f32
#pragma unroll 4
        for (int nt = 0; nt < 16; nt++) {
            int tl = nt >> 1;
            int t  = tb + tl;
            if (t >= TT) break;
            float d0 = 0.f, d1 = 0.f, d2 = 0.f, d3 = 0.f;
            const __half* zb = Zs + (nt * 8 + grp) * ZSH + 2 * thr;
#pragma unroll
            for (int kt = 0; kt < 8; kt++) {
                uint32_t b0 = *(const uint32_t*)(zb + kt * 16);
                uint32_t b1 = *(const uint32_t*)(zb + kt * 16 + 8);
                asm volatile(
                    "mma.sync.aligned.m16n8k16.row.col.f32.f16.f16.f32 "
                    "{%0,%1,%2,%3}, {%4,%5,%6,%7}, {%8,%9}, {%0,%1,%2,%3};"
                    : "+f"(d0), "+f"(d1), "+f"(d2), "+f"(d3)
                    : "r"(afr[kt][0]), "r"(afr[kt][1]), "r"(afr[kt][2]), "r"(afr[kt][3]),
                      "r"(b0), "r"(b1));
            }
            size_t ob = (size_t)t * NELEM + (size_t)(h0 + grp) * H
                      + a0 + (nt & 1) * 8 + 2 * thr;
            *(float2*)&out[ob]         = make_float2(d0, d1);
            *(float2*)&out[ob + 8 * H] = make_float2(d2, d3);
        }
    }
}

// ---------------------------------------------------------------------------
// Launch: prep -> scan0 -> combine -> fused(scan+GEMM)
// Output layout: zs_out (T*H*H floats) followed by os (T*H floats).
// ---------------------------------------------------------------------------
extern "C" void kernel_launch(void* const* d_in, const int* in_sizes, int n_in,
                              void* d_out, int out_size) {
    const float* in  = (const float*)d_in[0];   // input_sequence (8192,128)
    const float* lam = (const float*)d_in[1];   // Lambda_bar (128,128)
    const float* Cm  = (const float*)d_in[2];   // C_tilde (128,128)
    const float* wq  = (const float*)d_in[3];   // w_q (3,3)
    const float* Dv  = (const float*)d_in[4];   // D (3,)
    (void)in_sizes; (void)n_in; (void)out_size;

    float* out    = (float*)d_out;
    float* os_out = out + (size_t)TT * NELEM;

    // smem: Zs (halves, rounded up to float pairs) + Ys + Xs
    const int fused_smem =
        ((128 * ZSH + 1) / 2 + 8 * 384 + 8 * 48) * (int)sizeof(float);
    cudaFuncSetAttribute(fused_kernel, cudaFuncAttributeMaxDynamicSharedMemorySize,
                         fused_smem);

    prep_kernel<<<TT, H>>>(in, wq, Dv, os_out);
    scan0_kernel<<<dim3(8, NC), 256>>>(in, lam);
    combine_kernel<<<NELEM / 256, 256>>>(lam);
    fused_kernel<<<dim3(8, NC), 256, fused_smem>>>(in, lam, Cm, out);
}

// round 5
// speedup vs baseline: 4.0748x; 1.1775x over previous
#include <cuda_runtime.h>
#include <cuda_fp16.h>
#include <cstdint>

// Problem constants (fixed by the dataset)
#define H 128
#define TT 4095          // (8192-3)/2 + 1
#define NC 128           // scan chunks
#define LC 32            // chunk length (last chunk = 31)
#define NELEM (H * H)    // 16384 state elements
#define ZSH 136          // padded Zs row stride in halves (conflict-free)

// Scratch (allocation-free rule: __device__ globals)
static __device__ float g_Y[TT * 3 * H];   // Y[t][w][d] = (w_q @ X_t)[w,d]
static __device__ float g_S[NC * NELEM];   // chunk-local end states
static __device__ float g_cin[NC * NELEM]; // carry-in per chunk

static __device__ __forceinline__ uint32_t smem_u32(const void* p) {
    uint32_t a;
    asm("{ .reg .u64 t; cvta.to.shared.u64 t, %1; cvt.u32.u64 %0, t; }"
        : "=r"(a) : "l"(p));
    return a;
}

// ---------------------------------------------------------------------------
// Kernel 1: Y[t][w][:] = sum_v wq[w][v]*x[2t+v][:], os[t][:] = sum_w D[w]*x[2t+w][:]
// ---------------------------------------------------------------------------
__global__ void prep_kernel(const float* __restrict__ in,
                            const float* __restrict__ wq,
                            const float* __restrict__ Dv,
                            float* __restrict__ os_out) {
    int t = blockIdx.x;
    int d = threadIdx.x;
    float x0 = in[(2 * t + 0) * H + d];
    float x1 = in[(2 * t + 1) * H + d];
    float x2 = in[(2 * t + 2) * H + d];
    g_Y[(t * 3 + 0) * H + d] = wq[0] * x0 + wq[1] * x1 + wq[2] * x2;
    g_Y[(t * 3 + 1) * H + d] = wq[3] * x0 + wq[4] * x1 + wq[5] * x2;
    g_Y[(t * 3 + 2) * H + d] = wq[6] * x0 + wq[7] * x1 + wq[8] * x2;
    os_out[t * H + d] = Dv[0] * x0 + Dv[1] * x1 + Dv[2] * x2;
}

// ---------------------------------------------------------------------------
// Kernel 2: chunk-local scan (zero init), batch-staged.
// ---------------------------------------------------------------------------
__global__ __launch_bounds__(256) void scan0_kernel(const float* __restrict__ in,
                                                    const float* __restrict__ Lam) {
    __shared__ float Ys[8 * 384];
    __shared__ float Xs[8 * 48];

    int c   = blockIdx.y;
    int a0  = blockIdx.x * 16;
    int tid = threadIdx.x;
    int d   = tid & 127;
    int ah  = (tid >> 7) * 8;

    float z[8], lam[8];
#pragma unroll
    for (int k = 0; k < 8; k++) {
        lam[k] = Lam[(a0 + ah + k) * H + d];
        z[k]   = 0.0f;
    }

    int t0c = c * LC;
    int t1c = t0c + LC; if (t1c > TT) t1c = TT;

    for (int tb = t0c; tb < t1c; tb += 8) {
        int nvt = t1c - tb; if (nvt > 8) nvt = 8;
        for (int i = tid; i < nvt * 384; i += 256) Ys[i] = g_Y[tb * 384 + i];
        for (int i = tid; i < nvt * 48; i += 256) {
            int tl = i / 48, r = i % 48, w = r / 16, al = r % 16;
            Xs[i] = in[(2 * (tb + tl) + w) * H + a0 + al];
        }
        __syncthreads();
        for (int tl = 0; tl < nvt; tl++) {
            float y0 = Ys[tl * 384 + d];
            float y1 = Ys[tl * 384 + 128 + d];
            float y2 = Ys[tl * 384 + 256 + d];
            const float* xs = &Xs[tl * 48 + ah];
#pragma unroll
            for (int k = 0; k < 8; k++) {
                float u = xs[k] * y0 + xs[16 + k] * y1 + xs[32 + k] * y2;
                z[k] = fmaf(lam[k], z[k], u);
            }
        }
        __syncthreads();
    }

#pragma unroll
    for (int k = 0; k < 8; k++) g_S[c * NELEM + (a0 + ah + k) * H + d] = z[k];
}

// ---------------------------------------------------------------------------
// Kernel 3: sequential carry combine across chunks.
// ---------------------------------------------------------------------------
__global__ void combine_kernel(const float* __restrict__ Lam) {
    int e = blockIdx.x * 256 + threadIdx.x;
    float lam = Lam[e];
    float p = lam;  // lam^32 via 5 squarings
    p = p * p; p = p * p; p = p * p; p = p * p; p = p * p;
    float cin = 0.0f;
    for (int c = 0; c < NC; c++) {
        g_cin[c * NELEM + e] = cin;
        cin = fmaf(p, cin, g_S[c * NELEM + e]);
    }
}

// ---------------------------------------------------------------------------
// Kernel 4: FUSED seeded scan + FP16 mma.sync GEMM, m=32 warp tiles (B reuse x2).
//   scan threads: d2 = tid&63 (d = 2*d2, 2*d2+1), ag = tid>>6 (a = ag*4+j)
//                 -> half2 STS into Zs[ta][d], stride ZSH
//   gemm warps:   4(m) x 2(n); warp = 32 h-rows x 64 ta-cols; A (C) in regs.
// ---------------------------------------------------------------------------
__global__ __launch_bounds__(256, 2) void fused_kernel(const float* __restrict__ in,
                                                       const float* __restrict__ Lam,
                                                       const float* __restrict__ Cm,
                                                       float* __restrict__ out) {
    extern __shared__ float smem[];
    __half* Zs = (__half*)smem;                 // 128 * ZSH halves
    float*  Ys = smem + (128 * ZSH) / 2;        // 8 * 384 floats
    float*  Xs = Ys + 8 * 384;                  // 8 * 48 floats

    int tid = threadIdx.x;
    int c   = blockIdx.y;
    int a0  = blockIdx.x * 16;

    // scan mapping
    int d2 = tid & 63;
    int ag = tid >> 6;

    // gemm mapping
    int wrp = tid >> 5, l = tid & 31;
    int grp = l >> 2, thr = l & 3;
    int mg  = wrp & 3, ng = wrp >> 2;
    int h0  = mg * 32;

    // A fragments: C rows [h0, h0+32), fp16. 8 k-tiles x 8 half2 regs.
    uint32_t afr[8][8];
#pragma unroll
    for (int kt = 0; kt < 8; kt++) {
        int cb = kt * 16 + 2 * thr;
#pragma unroll
        for (int mt = 0; mt < 2; mt++) {
            const float* r0 = Cm + (h0 + mt * 16 + grp) * H;
            const float* r1 = Cm + (h0 + mt * 16 + grp + 8) * H;
            __half2 p0 = __floats2half2_rn(r0[cb],     r0[cb + 1]);
            __half2 p1 = __floats2half2_rn(r1[cb],     r1[cb + 1]);
            __half2 p2 = __floats2half2_rn(r0[cb + 8], r0[cb + 9]);
            __half2 p3 = __floats2half2_rn(r1[cb + 8], r1[cb + 9]);
            afr[kt][mt * 4 + 0] = *(uint32_t*)&p0;
            afr[kt][mt * 4 + 1] = *(uint32_t*)&p1;
            afr[kt][mt * 4 + 2] = *(uint32_t*)&p2;
            afr[kt][mt * 4 + 3] = *(uint32_t*)&p3;
        }
    }

    // scan state: 4 a x 2 d per thread
    float z[8], lam[8];
#pragma unroll
    for (int j = 0; j < 4; j++) {
        int a = a0 + ag * 4 + j;
        float2 lv = *(const float2*)&Lam[a * H + 2 * d2];
        float2 cv = *(const float2*)&g_cin[c * NELEM + a * H + 2 * d2];
        lam[j * 2]     = lv.x;  lam[j * 2 + 1] = lv.y;
        z[j * 2]       = cv.x;  z[j * 2 + 1]   = cv.y;
    }

    int t0c = c * LC;
    int t1c = t0c + LC; if (t1c > TT) t1c = TT;

    for (int tb = t0c; tb < t1c; tb += 8) {
        int nvt = t1c - tb; if (nvt > 8) nvt = 8;

        // stage Y (cp.async 16B) and X
        {
            const float* ysrc = g_Y + tb * 384;
            uint32_t ydst = smem_u32(Ys);
            int n16 = nvt * 96;          // 16B chunks
            for (int i = tid; i < n16; i += 256) {
                asm volatile("cp.async.ca.shared.global [%0], [%1], 16;"
                             :: "r"(ydst + i * 16), "l"(ysrc + i * 4));
            }
            asm volatile("cp.async.commit_group;");
        }
        for (int i = tid; i < nvt * 48; i += 256) {
            int tl = i / 48, r = i % 48, w = r / 16, al = r % 16;
            Xs[i] = in[(2 * (tb + tl) + w) * H + a0 + al];
        }
        asm volatile("cp.async.wait_group 0;");
        __syncthreads();   // Ys/Xs ready AND previous batch's GEMM done with Zs

        // scan nvt timesteps, half2 stores into Zs
        for (int tl = 0; tl < nvt; tl++) {
            float2 y0 = *(const float2*)&Ys[tl * 384 + 2 * d2];
            float2 y1 = *(const float2*)&Ys[tl * 384 + 128 + 2 * d2];
            float2 y2 = *(const float2*)&Ys[tl * 384 + 256 + 2 * d2];
            const float* xs = &Xs[tl * 48 + ag * 4];
#pragma unroll
            for (int j = 0; j < 4; j++) {
                float xa0 = xs[j], xa1 = xs[16 + j], xa2 = xs[32 + j];
                float u0 = xa0 * y0.x + xa1 * y1.x + xa2 * y2.x;
                float u1 = xa0 * y0.y + xa1 * y1.y + xa2 * y2.y;
                z[j * 2]     = fmaf(lam[j * 2],     z[j * 2],     u0);
                z[j * 2 + 1] = fmaf(lam[j * 2 + 1], z[j * 2 + 1], u1);
                *(__half2*)&Zs[(tl * 16 + ag * 4 + j) * ZSH + 2 * d2] =
                    __floats2half2_rn(z[j * 2], z[j * 2 + 1]);
            }
        }
        __syncthreads();   // Zs ready

        // GEMM: warp covers h [h0,h0+32) x ta [ng*64, ng*64+64)
        for (int nt = ng * 8; nt < ng * 8 + 8; nt++) {
            int tl = nt >> 1;
            int t  = tb + tl;
            if (t >= TT) break;
            float acc[8];
#pragma unroll
            for (int i = 0; i < 8; i++) acc[i] = 0.0f;
            const __half* zb = Zs + (nt * 8 + grp) * ZSH + 2 * thr;
#pragma unroll
            for (int kt = 0; kt < 8; kt++) {
                uint32_t b0 = *(const uint32_t*)(zb + kt * 16);
                uint32_t b1 = *(const uint32_t*)(zb + kt * 16 + 8);
                asm volatile(
                    "mma.sync.aligned.m16n8k16.row.col.f32.f16.f16.f32 "
                    "{%0,%1,%2,%3}, {%4,%5,%6,%7}, {%8,%9}, {%0,%1,%2,%3};"
                    : "+f"(acc[0]), "+f"(acc[1]), "+f"(acc[2]), "+f"(acc[3])
                    : "r"(afr[kt][0]), "r"(afr[kt][1]), "r"(afr[kt][2]), "r"(afr[kt][3]),
                      "r"(b0), "r"(b1));
                asm volatile(
                    "mma.sync.aligned.m16n8k16.row.col.f32.f16.f16.f32 "
                    "{%0,%1,%2,%3}, {%4,%5,%6,%7}, {%8,%9}, {%0,%1,%2,%3};"
                    : "+f"(acc[4]), "+f"(acc[5]), "+f"(acc[6]), "+f"(acc[7])
                    : "r"(afr[kt][4]), "r"(afr[kt][5]), "r"(afr[kt][6]), "r"(afr[kt][7]),
                      "r"(b0), "r"(b1));
            }
            float* ob = out + (size_t)t * NELEM + a0 + (nt & 1) * 8 + 2 * thr;
            asm volatile("st.global.cs.v2.f32 [%0], {%1,%2};"
                         :: "l"(ob + (size_t)(h0 + grp) * H), "f"(acc[0]), "f"(acc[1]));
            asm volatile("st.global.cs.v2.f32 [%0], {%1,%2};"
                         :: "l"(ob + (size_t)(h0 + grp + 8) * H), "f"(acc[2]), "f"(acc[3]));
            asm volatile("st.global.cs.v2.f32 [%0], {%1,%2};"
                         :: "l"(ob + (size_t)(h0 + 16 + grp) * H), "f"(acc[4]), "f"(acc[5]));
            asm volatile("st.global.cs.v2.f32 [%0], {%1,%2};"
                         :: "l"(ob + (size_t)(h0 + 24 + grp) * H), "f"(acc[6]), "f"(acc[7]));
        }
    }
}

// ---------------------------------------------------------------------------
// Launch: prep -> scan0 -> combine -> fused(scan+GEMM)
// Output layout: zs_out (T*H*H floats) followed by os (T*H floats).
// ---------------------------------------------------------------------------
extern "C" void kernel_launch(void* const* d_in, const int* in_sizes, int n_in,
                              void* d_out, int out_size) {
    const float* in  = (const float*)d_in[0];   // input_sequence (8192,128)
    const float* lam = (const float*)d_in[1];   // Lambda_bar (128,128)
    const float* Cm  = (const float*)d_in[2];   // C_tilde (128,128)
    const float* wq  = (const float*)d_in[3];   // w_q (3,3)
    const float* Dv  = (const float*)d_in[4];   // D (3,)
    (void)in_sizes; (void)n_in; (void)out_size;

    float* out    = (float*)d_out;
    float* os_out = out + (size_t)TT * NELEM;

    // smem: Zs halves (128*ZSH) + Ys + Xs
    const int fused_smem =
        ((128 * ZSH) / 2 + 8 * 384 + 8 * 48) * (int)sizeof(float);
    cudaFuncSetAttribute(fused_kernel, cudaFuncAttributeMaxDynamicSharedMemorySize,
                         fused_smem);

    prep_kernel<<<TT, H>>>(in, wq, Dv, os_out);
    scan0_kernel<<<dim3(8, NC), 256>>>(in, lam);
    combine_kernel<<<NELEM / 256, 256>>>(lam);
    fused_kernel<<<dim3(8, NC), 256, fused_smem>>>(in, lam, Cm, out);
}

// round 6
// speedup vs baseline: 4.3336x; 1.0635x over previous
#include <cuda_runtime.h>
#include <cuda_fp16.h>
#include <cstdint>

// Problem constants (fixed by the dataset)
#define H 128
#define TT 4095          // (8192-3)/2 + 1
#define NC 128           // scan chunks
#define LC 32            // chunk length (last chunk = 31)
#define NELEM (H * H)    // 16384 state elements
#define ZSH 136          // padded Zs row stride in halves (conflict-free)

// Scratch (allocation-free rule: __device__ globals)
static __device__ float g_Y[TT * 3 * H];   // Y[t][w][d] = (w_q @ X_t)[w,d]
static __device__ float g_S[NC * NELEM];   // chunk-local end states
static __device__ float g_cin[NC * NELEM]; // carry-in per chunk

// ---------------------------------------------------------------------------
// Kernel 1: Y[t][w][:] = sum_v wq[w][v]*x[2t+v][:], os[t][:] = sum_w D[w]*x[2t+w][:]
// ---------------------------------------------------------------------------
__global__ void prep_kernel(const float* __restrict__ in,
                            const float* __restrict__ wq,
                            const float* __restrict__ Dv,
                            float* __restrict__ os_out) {
    int t = blockIdx.x;
    int d = threadIdx.x;
    float x0 = in[(2 * t + 0) * H + d];
    float x1 = in[(2 * t + 1) * H + d];
    float x2 = in[(2 * t + 2) * H + d];
    g_Y[(t * 3 + 0) * H + d] = wq[0] * x0 + wq[1] * x1 + wq[2] * x2;
    g_Y[(t * 3 + 1) * H + d] = wq[3] * x0 + wq[4] * x1 + wq[5] * x2;
    g_Y[(t * 3 + 2) * H + d] = wq[6] * x0 + wq[7] * x1 + wq[8] * x2;
    os_out[t * H + d] = Dv[0] * x0 + Dv[1] * x1 + Dv[2] * x2;
}

// ---------------------------------------------------------------------------
// Kernel 2: chunk-local scan (zero init), batch-staged.
// ---------------------------------------------------------------------------
__global__ __launch_bounds__(256) void scan0_kernel(const float* __restrict__ in,
                                                    const float* __restrict__ Lam) {
    __shared__ float Ys[8 * 384];
    __shared__ float Xs[8 * 48];

    int c   = blockIdx.y;
    int a0  = blockIdx.x * 16;
    int tid = threadIdx.x;
    int d   = tid & 127;
    int ah  = (tid >> 7) * 8;

    float z[8], lam[8];
#pragma unroll
    for (int k = 0; k < 8; k++) {
        lam[k] = Lam[(a0 + ah + k) * H + d];
        z[k]   = 0.0f;
    }

    int t0c = c * LC;
    int t1c = t0c + LC; if (t1c > TT) t1c = TT;

    for (int tb = t0c; tb < t1c; tb += 8) {
        int nvt = t1c - tb; if (nvt > 8) nvt = 8;
        for (int i = tid; i < nvt * 384; i += 256) Ys[i] = g_Y[tb * 384 + i];
        for (int i = tid; i < nvt * 48; i += 256) {
            int tl = i / 48, r = i % 48, w = r / 16, al = r % 16;
            Xs[i] = in[(2 * (tb + tl) + w) * H + a0 + al];
        }
        __syncthreads();
        for (int tl = 0; tl < nvt; tl++) {
            float y0 = Ys[tl * 384 + d];
            float y1 = Ys[tl * 384 + 128 + d];
            float y2 = Ys[tl * 384 + 256 + d];
            const float* xs = &Xs[tl * 48 + ah];
#pragma unroll
            for (int k = 0; k < 8; k++) {
                float u = xs[k] * y0 + xs[16 + k] * y1 + xs[32 + k] * y2;
                z[k] = fmaf(lam[k], z[k], u);
            }
        }
        __syncthreads();
    }

#pragma unroll
    for (int k = 0; k < 8; k++) g_S[c * NELEM + (a0 + ah + k) * H + d] = z[k];
}

// ---------------------------------------------------------------------------
// Kernel 3: sequential carry combine across chunks.
// ---------------------------------------------------------------------------
__global__ void combine_kernel(const float* __restrict__ Lam) {
    int e = blockIdx.x * 256 + threadIdx.x;
    float lam = Lam[e];
    float p = lam;  // lam^32 via 5 squarings
    p = p * p; p = p * p; p = p * p; p = p * p; p = p * p;
    float cin = 0.0f;
    for (int c = 0; c < NC; c++) {
        g_cin[c * NELEM + e] = cin;
        cin = fmaf(p, cin, g_S[c * NELEM + e]);
    }
}

// ---------------------------------------------------------------------------
// Kernel 4: FUSED scan + GEMM, WARP-SPECIALIZED producer/consumer.
//   warps 0-3 (producers): seeded scan; thread owns 4a x 4d; Y via direct
//     LDG.128 from g_Y (no smem staging); writes fp16 Zs[buf] via STS.64.
//   warps 4-7 (consumers): fp16 m16n8k16 GEMM; warp = 32 h-rows x full 128 ta;
//     C A-frags register-resident; reads Zs[buf^1]; streams out via st.global.cs.
//   One __syncthreads per batch; producers run 1 batch ahead (double buffer).
// ---------------------------------------------------------------------------
__global__ __launch_bounds__(256, 2) void fused_kernel(const float* __restrict__ in,
                                                       const float* __restrict__ Lam,
                                                       const float* __restrict__ Cm,
                                                       float* __restrict__ out) {
    extern __shared__ float smem[];
    __half* ZsA = (__half*)smem;              // buffer 0: 128 * ZSH halves
    __half* ZsB = ZsA + 128 * ZSH;            // buffer 1

    int tid = threadIdx.x;
    int c   = blockIdx.y;
    int a0  = blockIdx.x * 16;
    int wrp = tid >> 5, l = tid & 31;

    int t0c = c * LC;
    int t1c = t0c + LC; if (t1c > TT) t1c = TT;
    int nb  = (t1c - t0c + 7) >> 3;   // always 4

    bool producer = (wrp < 4);

    // ---- producer state ----
    int pd4 = (l) * 4;            // d base 0..124 (lane -> 4 consecutive d)
    int pag = wrp & 3;            // a group 0..3 -> a = a0 + 4*pag + j
    float z[16], lam[16];
    if (producer) {
#pragma unroll
        for (int j = 0; j < 4; j++) {
            int a = a0 + pag * 4 + j;
            float4 lv = *(const float4*)&Lam[a * H + pd4];
            float4 cv = *(const float4*)&g_cin[c * NELEM + a * H + pd4];
            lam[j * 4 + 0] = lv.x; lam[j * 4 + 1] = lv.y;
            lam[j * 4 + 2] = lv.z; lam[j * 4 + 3] = lv.w;
            z[j * 4 + 0] = cv.x; z[j * 4 + 1] = cv.y;
            z[j * 4 + 2] = cv.z; z[j * 4 + 3] = cv.w;
        }
    }

    // ---- consumer state: A fragments (C rows [h0,h0+32), fp16) ----
    int grp = l >> 2, thr = l & 3;
    int mg  = wrp - 4;            // 0..3
    int h0  = mg * 32;
    uint32_t afr[8][8];
    if (!producer) {
#pragma unroll
        for (int kt = 0; kt < 8; kt++) {
            int cb = kt * 16 + 2 * thr;
#pragma unroll
            for (int mt = 0; mt < 2; mt++) {
                const float* r0 = Cm + (h0 + mt * 16 + grp) * H;
                const float* r1 = Cm + (h0 + mt * 16 + grp + 8) * H;
                __half2 p0 = __floats2half2_rn(r0[cb],     r0[cb + 1]);
                __half2 p1 = __floats2half2_rn(r1[cb],     r1[cb + 1]);
                __half2 p2 = __floats2half2_rn(r0[cb + 8], r0[cb + 9]);
                __half2 p3 = __floats2half2_rn(r1[cb + 8], r1[cb + 9]);
                afr[kt][mt * 4 + 0] = *(uint32_t*)&p0;
                afr[kt][mt * 4 + 1] = *(uint32_t*)&p1;
                afr[kt][mt * 4 + 2] = *(uint32_t*)&p2;
                afr[kt][mt * 4 + 3] = *(uint32_t*)&p3;
            }
        }
    }

    for (int ib = 0; ib <= nb; ib++) {
        if (producer && ib < nb) {
            int tb  = t0c + ib * 8;
            int nvt = t1c - tb; if (nvt > 8) nvt = 8;
            __half* Zb = (ib & 1) ? ZsB : ZsA;
#pragma unroll
            for (int tl = 0; tl < 8; tl++) {
                if (tl >= nvt) break;
                int t = tb + tl;
                const float* yb = g_Y + t * 384;
                float4 y0 = *(const float4*)(yb + pd4);
                float4 y1 = *(const float4*)(yb + 128 + pd4);
                float4 y2 = *(const float4*)(yb + 256 + pd4);
                const float* xb = in + (size_t)(2 * t) * H + a0 + pag * 4;
#pragma unroll
                for (int j = 0; j < 4; j++) {
                    float xa = __ldg(xb + j);
                    float xm = __ldg(xb + H + j);
                    float xc = __ldg(xb + 2 * H + j);
                    float u0 = xa * y0.x + xm * y1.x + xc * y2.x;
                    float u1 = xa * y0.y + xm * y1.y + xc * y2.y;
                    float u2 = xa * y0.z + xm * y1.z + xc * y2.z;
                    float u3 = xa * y0.w + xm * y1.w + xc * y2.w;
                    z[j * 4 + 0] = fmaf(lam[j * 4 + 0], z[j * 4 + 0], u0);
                    z[j * 4 + 1] = fmaf(lam[j * 4 + 1], z[j * 4 + 1], u1);
                    z[j * 4 + 2] = fmaf(lam[j * 4 + 2], z[j * 4 + 2], u2);
                    z[j * 4 + 3] = fmaf(lam[j * 4 + 3], z[j * 4 + 3], u3);
                    __half2 p0 = __floats2half2_rn(z[j * 4 + 0], z[j * 4 + 1]);
                    __half2 p1 = __floats2half2_rn(z[j * 4 + 2], z[j * 4 + 3]);
                    uint2 pk;
                    pk.x = *(uint32_t*)&p0;
                    pk.y = *(uint32_t*)&p1;
                    *(uint2*)&Zb[(tl * 16 + pag * 4 + j) * ZSH + pd4] = pk;
                }
            }
        } else if (!producer && ib > 0) {
            int jb = ib - 1;
            int tb = t0c + jb * 8;
            __half* Zb = (jb & 1) ? ZsB : ZsA;
            for (int nt = 0; nt < 16; nt++) {
                int t = tb + (nt >> 1);
                if (t >= TT) break;
                float acc[8];
#pragma unroll
                for (int i = 0; i < 8; i++) acc[i] = 0.0f;
                const __half* zb = Zb + (nt * 8 + grp) * ZSH + 2 * thr;
#pragma unroll
                for (int kt = 0; kt < 8; kt++) {
                    uint32_t b0 = *(const uint32_t*)(zb + kt * 16);
                    uint32_t b1 = *(const uint32_t*)(zb + kt * 16 + 8);
                    asm volatile(
                        "mma.sync.aligned.m16n8k16.row.col.f32.f16.f16.f32 "
                        "{%0,%1,%2,%3}, {%4,%5,%6,%7}, {%8,%9}, {%0,%1,%2,%3};"
                        : "+f"(acc[0]), "+f"(acc[1]), "+f"(acc[2]), "+f"(acc[3])
                        : "r"(afr[kt][0]), "r"(afr[kt][1]), "r"(afr[kt][2]),
                          "r"(afr[kt][3]), "r"(b0), "r"(b1));
                    asm volatile(
                        "mma.sync.aligned.m16n8k16.row.col.f32.f16.f16.f32 "
                        "{%0,%1,%2,%3}, {%4,%5,%6,%7}, {%8,%9}, {%0,%1,%2,%3};"
                        : "+f"(acc[4]), "+f"(acc[5]), "+f"(acc[6]), "+f"(acc[7])
                        : "r"(afr[kt][4]), "r"(afr[kt][5]), "r"(afr[kt][6]),
                          "r"(afr[kt][7]), "r"(b0), "r"(b1));
                }
                float* ob = out + (size_t)t * NELEM + a0 + (nt & 1) * 8 + 2 * thr;
                asm volatile("st.global.cs.v2.f32 [%0], {%1,%2};"
                             :: "l"(ob + (size_t)(h0 + grp) * H),
                                "f"(acc[0]), "f"(acc[1]));
                asm volatile("st.global.cs.v2.f32 [%0], {%1,%2};"
                             :: "l"(ob + (size_t)(h0 + grp + 8) * H),
                                "f"(acc[2]), "f"(acc[3]));
                asm volatile("st.global.cs.v2.f32 [%0], {%1,%2};"
                             :: "l"(ob + (size_t)(h0 + 16 + grp) * H),
                                "f"(acc[4]), "f"(acc[5]));
                asm volatile("st.global.cs.v2.f32 [%0], {%1,%2};"
                             :: "l"(ob + (size_t)(h0 + 24 + grp) * H),
                                "f"(acc[6]), "f"(acc[7]));
            }
        }
        __syncthreads();
    }
}

// ---------------------------------------------------------------------------
// Launch: prep -> scan0 -> combine -> fused(scan+GEMM, warp-specialized)
// Output layout: zs_out (T*H*H floats) followed by os (T*H floats).
// ---------------------------------------------------------------------------
extern "C" void kernel_launch(void* const* d_in, const int* in_sizes, int n_in,
                              void* d_out, int out_size) {
    const float* in  = (const float*)d_in[0];   // input_sequence (8192,128)
    const float* lam = (const float*)d_in[1];   // Lambda_bar (128,128)
    const float* Cm  = (const float*)d_in[2];   // C_tilde (128,128)
    const float* wq  = (const float*)d_in[3];   // w_q (3,3)
    const float* Dv  = (const float*)d_in[4];   // D (3,)
    (void)in_sizes; (void)n_in; (void)out_size;

    float* out    = (float*)d_out;
    float* os_out = out + (size_t)TT * NELEM;

    // smem: double-buffered Zs (halves)
    const int fused_smem = 2 * 128 * ZSH * (int)sizeof(__half);
    cudaFuncSetAttribute(fused_kernel, cudaFuncAttributeMaxDynamicSharedMemorySize,
                         fused_smem);

    prep_kernel<<<TT, H>>>(in, wq, Dv, os_out);
    scan0_kernel<<<dim3(8, NC), 256>>>(in, lam);
    combine_kernel<<<NELEM / 256, 256>>>(lam);
    fused_kernel<<<dim3(8, NC), 256, fused_smem>>>(in, lam, Cm, out);
}